// round 8
// baseline (speedup 1.0000x reference)
#include <cuda_runtime.h>
#include <cuda_fp16.h>
#include <cstdint>

#define NN      100000
#define EE      1600000
#define CC      25000
#define PF      4
#define BM_WORDS 9765625u
#define SUMW     152588u       // ceil(BM_WORDS / 64)
#define WPB      2048
#define NBLK     4769
#define SHB      98

#define XNEW_OFF  0
#define POS_OFF   3200000
#define IDX_OFF   3275000
#define ATTR_OFF  6475000
#define BATCH_OFF 11275000

#define VALM 0x3FFFFFFFu
#define AGGF 0x40000000u
#define PREF 0x80000000u

static __device__ unsigned long long g_bitmap[BM_WORDS];
static __device__ unsigned long long g_summary[SUMW];
static __device__ float    g_cagg_x[CC * 128];
static __device__ float    g_cagg_e[CC * 4];
static __device__ float    g_newpos[CC * 3];
static __device__ float    g_W1[128 * 128];
static __device__ float    g_W2[3 * 128];
static __device__ unsigned g_hist[CC];
static __device__ unsigned g_start[CC];
static __device__ unsigned g_cursor[CC];
static __device__ int      g_binned_src[EE];
static __device__ unsigned g_ubState[NBLK];
static __device__ unsigned g_shState[SHB];
static __device__ uint2    g_xh[NN * 32];

// ---------------------------------------------------------------------------
__device__ __forceinline__ unsigned lookback(unsigned* state, int b, unsigned agg) {
    if (b == 0) {
        __threadfence();
        atomicExch(&state[0], PREF | agg);
        return 0u;
    }
    atomicExch(&state[b], AGGF | agg);
    unsigned prefix = 0;
    int i = b - 1;
    while (true) {
        unsigned s;
        do { s = atomicAdd(&state[i], 0u); } while (!(s & (AGGF | PREF)));
        prefix += s & VALM;
        if (s & PREF) break;
        i--;
    }
    __threadfence();
    atomicExch(&state[b], PREF | (agg + prefix));
    return prefix;
}

__device__ __forceinline__ unsigned block_excl_scan256(unsigned v, unsigned* s_warp,
                                                       unsigned* total) {
    unsigned lane = threadIdx.x & 31, wid = threadIdx.x >> 5;
    unsigned x = v;
    #pragma unroll
    for (int o = 1; o < 32; o <<= 1) {
        unsigned y = __shfl_up_sync(0xffffffffu, x, o);
        if (lane >= o) x += y;
    }
    if (lane == 31) s_warp[wid] = x;
    __syncthreads();
    if (wid == 0) {
        unsigned t = (lane < 8) ? s_warp[lane] : 0u;
        #pragma unroll
        for (int o = 1; o < 8; o <<= 1) {
            unsigned y = __shfl_up_sync(0xffffffffu, t, o);
            if (lane >= o) t += y;
        }
        if (lane < 8) s_warp[lane] = t;
    }
    __syncthreads();
    unsigned warpBase = wid ? s_warp[wid - 1] : 0u;
    unsigned excl = warpBase + x - v;
    *total = s_warp[7];
    __syncthreads();
    return excl;
}

// ---------------------------------------------------------------------------
// K_xh: convert x (f32) to half2
__global__ __launch_bounds__(256) void k_xh(const float* __restrict__ x) {
    int t = blockIdx.x * 256 + threadIdx.x;
    const int TOT = NN * 32;
    const int S = gridDim.x * 256;
    const float4* x4 = (const float4*)x;
    for (int i = t; i < TOT; i += S) {
        float4 v = __ldg(&x4[i]);
        __half2 h0 = __floats2half2_rn(v.x, v.y);
        __half2 h1 = __floats2half2_rn(v.z, v.w);
        uint2 u;
        u.x = *(unsigned*)&h0;
        u.y = *(unsigned*)&h1;
        g_xh[i] = u;
    }
}

// ---------------------------------------------------------------------------
// K_init: [0,98): new_pos/new_batch ; [98,229): weight GEMMs ; [229,269): zeros
__global__ void k_init(const float* __restrict__ pos,
                       const int* __restrict__ batch,
                       const float* __restrict__ Wc,
                       const float* __restrict__ We,
                       const float* __restrict__ Wg,
                       float* __restrict__ out) {
    if (blockIdx.x < 98) {
        int c = blockIdx.x * 256 + threadIdx.x;
        if (c >= CC) return;
        float s0 = 0.f, s1 = 0.f, s2 = 0.f;
        int bmax = -2147483647;
        #pragma unroll
        for (int i = 0; i < PF; i++) {
            int n = c * PF + i;
            s0 += pos[n * 3 + 0];
            s1 += pos[n * 3 + 1];
            s2 += pos[n * 3 + 2];
            int b = batch[n];
            bmax = b > bmax ? b : bmax;
        }
        s0 *= 0.25f; s1 *= 0.25f; s2 *= 0.25f;
        g_newpos[c * 3 + 0] = s0;
        g_newpos[c * 3 + 1] = s1;
        g_newpos[c * 3 + 2] = s2;
        out[POS_OFF + c * 3 + 0] = s0;
        out[POS_OFF + c * 3 + 1] = s1;
        out[POS_OFF + c * 3 + 2] = s2;
        out[BATCH_OFF + c] = (float)bmax;
    } else if (blockIdx.x < 229) {
        int i = blockIdx.x - 98;
        int j = threadIdx.x;
        if (j >= 128) return;
        if (i < 128) {
            float s = 0.f;
            #pragma unroll 8
            for (int k = 0; k < 128; k++) s += Wc[i * 144 + 16 + k] * Wg[k * 128 + j];
            g_W1[i * 128 + j] = s;
        } else {
            int r = i - 128;
            float s = 0.f;
            #pragma unroll 8
            for (int k = 0; k < 128; k++) s += We[r * 144 + 16 + k] * Wg[k * 128 + j];
            g_W2[r * 128 + j] = s;
        }
    } else {
        int t = (blockIdx.x - 229) * 256 + threadIdx.x;
        const int S = 40 * 256;
        for (int i = t; i < CC * 4; i += S) g_cagg_e[i] = 0.f;
        for (int i = t; i < CC; i += S) g_hist[i] = 0u;
        for (int i = t; i < NBLK; i += S) g_ubState[i] = 0u;
        for (int i = t; i < SHB; i += S) g_shState[i] = 0u;
    }
}

// ---------------------------------------------------------------------------
// K_hist (fused): bitmap + summary set, cluster histogram, edge_attr atomics
__global__ __launch_bounds__(256) void k_hist(const int* __restrict__ ei,
                                              const float* __restrict__ ea) {
    int base = blockIdx.x * 1024 + threadIdx.x;
    int sv[4], dv[4]; bool ok[4];
    #pragma unroll
    for (int i = 0; i < 4; i++) {
        int e = base + i * 256;
        ok[i] = e < EE;
        sv[i] = ok[i] ? ei[e] : 0;
        dv[i] = ok[i] ? ei[EE + e] : 0;
    }
    #pragma unroll
    for (int i = 0; i < 4; i++) {
        if (!ok[i]) continue;
        int e = base + i * 256;
        int c = dv[i] >> 2;
        unsigned enc = (unsigned)(sv[i] >> 2) * (unsigned)CC + (unsigned)c;
        unsigned wi = enc >> 6;
        atomicOr(&g_bitmap[wi], 1ull << (enc & 63));
        atomicOr(&g_summary[wi >> 6], 1ull << (wi & 63));
        atomicAdd(&g_hist[c], 1u);
        atomicAdd(&g_cagg_e[c * 4 + 0], ea[3 * e + 0]);
        atomicAdd(&g_cagg_e[c * 4 + 1], ea[3 * e + 1]);
        atomicAdd(&g_cagg_e[c * 4 + 2], ea[3 * e + 2]);
    }
}

// ---------------------------------------------------------------------------
// K_scanH: exclusive scan of cluster counts (decoupled lookback)
__global__ __launch_bounds__(256) void k_scanH() {
    __shared__ unsigned s_warp[8];
    __shared__ unsigned sh_base;
    int b = blockIdx.x, tid = threadIdx.x;
    int idx = b * 256 + tid;
    unsigned v = (idx < CC) ? g_hist[idx] : 0u;
    unsigned total;
    unsigned excl = block_excl_scan256(v, s_warp, &total);
    if (tid == 0) sh_base = lookback(g_shState, b, total);
    __syncthreads();
    if (idx < CC) {
        unsigned st = sh_base + excl;
        g_start[idx] = st;
        g_cursor[idx] = st;
    }
}

// ---------------------------------------------------------------------------
// K_fill: place srcs into dst-cluster bins (4 edges/thread)
__global__ __launch_bounds__(256) void k_fill(const int* __restrict__ ei) {
    int base = blockIdx.x * 1024 + threadIdx.x;
    int sv[4]; unsigned p[4]; bool ok[4];
    #pragma unroll
    for (int i = 0; i < 4; i++) {
        int e = base + i * 256;
        ok[i] = e < EE;
        sv[i] = ok[i] ? ei[e] : 0;
        int c = ok[i] ? (ei[EE + e] >> 2) : 0;
        p[i] = ok[i] ? atomicAdd(&g_cursor[c], 1u) : 0u;
    }
    #pragma unroll
    for (int i = 0; i < 4; i++)
        if (ok[i]) g_binned_src[p[i]] = sv[i];
}

// ---------------------------------------------------------------------------
// K_cluster: one warp per cluster; fp16 gather, fp32 accumulate
__global__ __launch_bounds__(256) void k_cluster() {
    int warp = (blockIdx.x * 256 + threadIdx.x) >> 5;
    int lane = threadIdx.x & 31;
    if (warp >= CC) return;
    unsigned base = g_start[warp];
    unsigned cnt = g_hist[warp];
    float4 acc = make_float4(0.f, 0.f, 0.f, 0.f);

    unsigned k = 0;
    for (; k + 32 <= cnt; k += 32) {
        int s = g_binned_src[base + k + lane];
        #pragma unroll
        for (int j = 0; j < 32; j++) {
            int sb = __shfl_sync(0xffffffffu, s, j);
            uint2 u = __ldg(&g_xh[sb * 32 + lane]);
            float2 f0 = __half22float2(*(__half2*)&u.x);
            float2 f1 = __half22float2(*(__half2*)&u.y);
            acc.x += f0.x; acc.y += f0.y; acc.z += f1.x; acc.w += f1.y;
        }
    }
    int rem = (int)(cnt - k);
    if (rem > 0) {
        int s = (lane < rem) ? g_binned_src[base + k + lane] : 0;
        for (int j = 0; j < rem; j++) {
            int sb = __shfl_sync(0xffffffffu, s, j);
            uint2 u = __ldg(&g_xh[sb * 32 + lane]);
            float2 f0 = __half22float2(*(__half2*)&u.x);
            float2 f1 = __half22float2(*(__half2*)&u.y);
            acc.x += f0.x; acc.y += f0.y; acc.z += f1.x; acc.w += f1.y;
        }
    }
    ((float4*)g_cagg_x)[(size_t)warp * 32 + lane] = acc;
}

// ---------------------------------------------------------------------------
// K_uniq: summary-guided count + lookback scan + sorted emit; self-cleans both
__global__ __launch_bounds__(256) void k_uniq(float* __restrict__ out) {
    __shared__ unsigned s_warp[8];
    __shared__ unsigned sh_base;
    int b = blockIdx.x, tid = threadIdx.x;
    unsigned sIdx = (unsigned)b * 32u + (unsigned)(tid >> 3);
    unsigned long long sw = (sIdx < SUMW) ? g_summary[sIdx] : 0ull;
    unsigned sbyte = (unsigned)(sw >> ((tid & 7) * 8)) & 0xFFu;
    size_t wbase = (size_t)b * WPB + (size_t)tid * 8;

    unsigned long long w[8];
    unsigned cnt = 0;
    #pragma unroll
    for (int j = 0; j < 8; j++) {
        w[j] = (sbyte >> j) & 1u ? g_bitmap[wbase + j] : 0ull;
        cnt += (unsigned)__popcll(w[j]);
    }
    unsigned total;
    unsigned excl = block_excl_scan256(cnt, s_warp, &total);
    if (tid == 0) sh_base = lookback(g_ubState, b, total);
    __syncthreads();
    // all co-readers of this summary word are past their loads (scan barriers)
    if ((tid & 7) == 0 && sw) g_summary[sIdx] = 0ull;
    unsigned p = sh_base + excl;

    #pragma unroll
    for (int j = 0; j < 8; j++) {
        unsigned long long wv = w[j];
        if (!wv) continue;
        size_t wi = wbase + j;
        g_bitmap[wi] = 0ull;
        while (wv) {
            int bit = __ffsll((long long)wv) - 1;
            wv &= wv - 1;
            unsigned v = (unsigned)wi * 64u + (unsigned)bit;
            unsigned sc = v / (unsigned)CC;
            unsigned dc = v - sc * (unsigned)CC;
            out[IDX_OFF + p]      = (float)sc;
            out[IDX_OFF + EE + p] = (float)dc;
            out[ATTR_OFF + 3 * p + 0] = g_newpos[dc * 3 + 0] - g_newpos[sc * 3 + 0];
            out[ATTR_OFF + 3 * p + 1] = g_newpos[dc * 3 + 1] - g_newpos[sc * 3 + 1];
            out[ATTR_OFF + 3 * p + 2] = g_newpos[dc * 3 + 2] - g_newpos[sc * 3 + 2];
            p++;
        }
    }
}

// ---------------------------------------------------------------------------
// K_tail: zero unused tail of idx/attr outputs
__global__ __launch_bounds__(256) void k_tail(float* __restrict__ out) {
    unsigned U = g_ubState[NBLK - 1] & VALM;
    int t = blockIdx.x * 256 + threadIdx.x;
    const int S = 64 * 256;
    for (int p = U + t; p < EE; p += S) {
        out[IDX_OFF + p] = 0.f;
        out[IDX_OFF + EE + p] = 0.f;
        out[ATTR_OFF + 3 * p + 0] = 0.f;
        out[ATTR_OFF + 3 * p + 1] = 0.f;
        out[ATTR_OFF + 3 * p + 2] = 0.f;
    }
}

// ---------------------------------------------------------------------------
// K_gemm: x_new = (cagg_x @ W1 + cagg_e @ W2) / PF
__global__ __launch_bounds__(256) void k_gemm(float* __restrict__ out) {
    __shared__ float s_rows[16][128];
    int col = threadIdx.x & 127;
    int ty = threadIdx.x >> 7;
    int r0 = blockIdx.x * 16;
    for (int i = threadIdx.x; i < 16 * 128; i += 256) {
        int rr = i >> 7, cc = i & 127;
        int gr = r0 + rr;
        s_rows[rr][cc] = (gr < CC) ? g_cagg_x[(size_t)gr * 128 + cc] : 0.f;
    }
    __syncthreads();
    float acc[8] = {0.f, 0.f, 0.f, 0.f, 0.f, 0.f, 0.f, 0.f};
    #pragma unroll 8
    for (int k = 0; k < 128; k += 4) {
        float w0 = __ldg(&g_W1[(k + 0) * 128 + col]);
        float w1 = __ldg(&g_W1[(k + 1) * 128 + col]);
        float w2 = __ldg(&g_W1[(k + 2) * 128 + col]);
        float w3 = __ldg(&g_W1[(k + 3) * 128 + col]);
        #pragma unroll
        for (int r = 0; r < 8; r++) {
            float4 cv = *(const float4*)&s_rows[ty * 8 + r][k];
            acc[r] += cv.x * w0 + cv.y * w1 + cv.z * w2 + cv.w * w3;
        }
    }
    float e0 = __ldg(&g_W2[0 * 128 + col]);
    float e1 = __ldg(&g_W2[1 * 128 + col]);
    float e2 = __ldg(&g_W2[2 * 128 + col]);
    #pragma unroll
    for (int r = 0; r < 8; r++) {
        int gr = r0 + ty * 8 + r;
        if (gr < CC) {
            float ce0 = g_cagg_e[gr * 4 + 0];
            float ce1 = g_cagg_e[gr * 4 + 1];
            float ce2 = g_cagg_e[gr * 4 + 2];
            float res = (acc[r] + ce0 * e0 + ce1 * e1 + ce2 * e2) * 0.25f;
            out[XNEW_OFF + (size_t)gr * 128 + col] = res;
        }
    }
}

// ---------------------------------------------------------------------------
extern "C" void kernel_launch(void* const* d_in, const int* in_sizes, int n_in,
                              void* d_out, int out_size) {
    const float* x   = (const float*)d_in[0];
    const float* pos = (const float*)d_in[1];
    const int*   ei  = (const int*)d_in[2];
    const float* ea  = (const float*)d_in[3];
    const int*   bat = (const int*)d_in[4];
    const float* Wc  = (const float*)d_in[5];
    const float* We  = (const float*)d_in[6];
    const float* Wg  = (const float*)d_in[8];
    float* out = (float*)d_out;

    static cudaStream_t s1 = nullptr, s2 = nullptr;
    static cudaEvent_t eT = nullptr, eF = nullptr, eJ = nullptr, eX = nullptr;
    if (s1 == nullptr) {
        cudaStreamCreate(&s1);
        cudaStreamCreate(&s2);
        cudaEventCreateWithFlags(&eT, cudaEventDisableTiming);
        cudaEventCreateWithFlags(&eF, cudaEventDisableTiming);
        cudaEventCreateWithFlags(&eJ, cudaEventDisableTiming);
        cudaEventCreateWithFlags(&eX, cudaEventDisableTiming);
    }

    // fork conversion stream immediately (depends only on input x)
    cudaEventRecord(eT, 0);
    cudaStreamWaitEvent(s2, eT, 0);
    k_xh<<<3200, 256, 0, s2>>>(x);
    cudaEventRecord(eX, s2);

    // main: init -> fused hist(+bitmap/summary)
    k_init<<<269, 256>>>(pos, bat, Wc, We, Wg, out);
    k_hist<<<(EE + 1023) / 1024, 256>>>(ei, ea);

    // fork side stream after hist: uniq -> tail
    cudaEventRecord(eF, 0);
    cudaStreamWaitEvent(s1, eF, 0);
    k_uniq<<<NBLK, 256, 0, s1>>>(out);
    k_tail<<<64, 256, 0, s1>>>(out);

    // main: scan -> fill -> (join xh) -> cluster -> gemm
    k_scanH<<<SHB, 256>>>();
    k_fill<<<(EE + 1023) / 1024, 256>>>(ei);
    cudaStreamWaitEvent(0, eX, 0);
    k_cluster<<<(CC * 32 + 255) / 256, 256>>>();
    k_gemm<<<(CC + 15) / 16, 256>>>(out);

    cudaEventRecord(eJ, s1);
    cudaStreamWaitEvent(0, eJ, 0);
}

// round 9
// speedup vs baseline: 1.1997x; 1.1997x over previous
#include <cuda_runtime.h>
#include <cuda_fp16.h>
#include <cstdint>

#define NN      100000
#define EE      1600000
#define CC      25000
#define PF      4
#define BM_WORDS 9765625u
#define SUMW     152588u
#define WPB      2048
#define NBLK     4769
#define SHB      98

#define XNEW_OFF  0
#define POS_OFF   3200000
#define IDX_OFF   3275000
#define ATTR_OFF  6475000
#define BATCH_OFF 11275000

#define VALM 0x3FFFFFFFu
#define AGGF 0x40000000u
#define PREF 0x80000000u

static __device__ unsigned long long g_bitmap[BM_WORDS];
static __device__ unsigned long long g_summary[SUMW];
static __device__ float    g_cagg_x[CC * 128];
static __device__ float    g_cagg_e[CC * 4];
static __device__ float    g_newpos[CC * 3];
static __device__ float    g_W1[128 * 128];
static __device__ float    g_W2[3 * 128];
static __device__ unsigned g_hist[CC];
static __device__ unsigned g_start[CC];
static __device__ unsigned g_cursor[CC];
static __device__ int      g_binned_src[EE];
static __device__ unsigned g_ubState[NBLK];
static __device__ unsigned g_shState[SHB];
static __device__ uint2    g_xh[NN * 32];

// ---------------------------------------------------------------------------
// Warp-parallel decoupled lookback: warp 0 calls; returns exclusive prefix to
// all lanes. 32 predecessor states polled per step.
__device__ __forceinline__ unsigned lookback_warp(unsigned* state, int b, unsigned agg) {
    int lane = threadIdx.x & 31;
    if (b == 0) {
        if (lane == 0) { __threadfence(); atomicExch(&state[0], PREF | agg); }
        return 0u;
    }
    if (lane == 0) atomicExch(&state[b], AGGF | agg);
    unsigned prefix = 0;
    int end = b;
    while (true) {
        int idx = end - 1 - lane;
        unsigned s;
        do {
            s = (idx >= 0) ? atomicAdd(&state[idx], 0u) : PREF;
        } while (!(s & (AGGF | PREF)));
        unsigned pmask = __ballot_sync(0xffffffffu, (s & PREF) != 0u);
        if (pmask) {
            int firstP = __ffs(pmask) - 1;        // closest PREF
            unsigned contrib = (lane <= firstP) ? (s & VALM) : 0u;
            #pragma unroll
            for (int o = 16; o; o >>= 1) contrib += __shfl_down_sync(0xffffffffu, contrib, o);
            contrib = __shfl_sync(0xffffffffu, contrib, 0);
            prefix += contrib;
            break;
        } else {
            unsigned contrib = s & VALM;
            #pragma unroll
            for (int o = 16; o; o >>= 1) contrib += __shfl_down_sync(0xffffffffu, contrib, o);
            contrib = __shfl_sync(0xffffffffu, contrib, 0);
            prefix += contrib;
            end -= 32;
        }
    }
    if (lane == 0) { __threadfence(); atomicExch(&state[b], PREF | (agg + prefix)); }
    return prefix;
}

__device__ __forceinline__ unsigned block_excl_scan256(unsigned v, unsigned* s_warp,
                                                       unsigned* total) {
    unsigned lane = threadIdx.x & 31, wid = threadIdx.x >> 5;
    unsigned x = v;
    #pragma unroll
    for (int o = 1; o < 32; o <<= 1) {
        unsigned y = __shfl_up_sync(0xffffffffu, x, o);
        if (lane >= o) x += y;
    }
    if (lane == 31) s_warp[wid] = x;
    __syncthreads();
    if (wid == 0) {
        unsigned t = (lane < 8) ? s_warp[lane] : 0u;
        #pragma unroll
        for (int o = 1; o < 8; o <<= 1) {
            unsigned y = __shfl_up_sync(0xffffffffu, t, o);
            if (lane >= o) t += y;
        }
        if (lane < 8) s_warp[lane] = t;
    }
    __syncthreads();
    unsigned warpBase = wid ? s_warp[wid - 1] : 0u;
    unsigned excl = warpBase + x - v;
    *total = s_warp[7];
    __syncthreads();
    return excl;
}

// ---------------------------------------------------------------------------
__global__ __launch_bounds__(256) void k_xh(const float* __restrict__ x) {
    int t = blockIdx.x * 256 + threadIdx.x;
    const int TOT = NN * 32;
    const int S = gridDim.x * 256;
    const float4* x4 = (const float4*)x;
    for (int i = t; i < TOT; i += S) {
        float4 v = __ldg(&x4[i]);
        __half2 h0 = __floats2half2_rn(v.x, v.y);
        __half2 h1 = __floats2half2_rn(v.z, v.w);
        uint2 u;
        u.x = *(unsigned*)&h0;
        u.y = *(unsigned*)&h1;
        g_xh[i] = u;
    }
}

// ---------------------------------------------------------------------------
__global__ void k_init(const float* __restrict__ pos,
                       const int* __restrict__ batch,
                       const float* __restrict__ Wc,
                       const float* __restrict__ We,
                       const float* __restrict__ Wg,
                       float* __restrict__ out) {
    if (blockIdx.x < 98) {
        int c = blockIdx.x * 256 + threadIdx.x;
        if (c >= CC) return;
        float s0 = 0.f, s1 = 0.f, s2 = 0.f;
        int bmax = -2147483647;
        #pragma unroll
        for (int i = 0; i < PF; i++) {
            int n = c * PF + i;
            s0 += pos[n * 3 + 0];
            s1 += pos[n * 3 + 1];
            s2 += pos[n * 3 + 2];
            int b = batch[n];
            bmax = b > bmax ? b : bmax;
        }
        s0 *= 0.25f; s1 *= 0.25f; s2 *= 0.25f;
        g_newpos[c * 3 + 0] = s0;
        g_newpos[c * 3 + 1] = s1;
        g_newpos[c * 3 + 2] = s2;
        out[POS_OFF + c * 3 + 0] = s0;
        out[POS_OFF + c * 3 + 1] = s1;
        out[POS_OFF + c * 3 + 2] = s2;
        out[BATCH_OFF + c] = (float)bmax;
    } else if (blockIdx.x < 229) {
        int i = blockIdx.x - 98;
        int j = threadIdx.x;
        if (j >= 128) return;
        if (i < 128) {
            float s = 0.f;
            #pragma unroll 8
            for (int k = 0; k < 128; k++) s += Wc[i * 144 + 16 + k] * Wg[k * 128 + j];
            g_W1[i * 128 + j] = s;
        } else {
            int r = i - 128;
            float s = 0.f;
            #pragma unroll 8
            for (int k = 0; k < 128; k++) s += We[r * 144 + 16 + k] * Wg[k * 128 + j];
            g_W2[r * 128 + j] = s;
        }
    } else {
        int t = (blockIdx.x - 229) * 256 + threadIdx.x;
        const int S = 40 * 256;
        for (int i = t; i < CC * 4; i += S) g_cagg_e[i] = 0.f;
        for (int i = t; i < CC; i += S) g_hist[i] = 0u;
        for (int i = t; i < NBLK; i += S) g_ubState[i] = 0u;
        for (int i = t; i < SHB; i += S) g_shState[i] = 0u;
    }
}

// ---------------------------------------------------------------------------
__global__ __launch_bounds__(256) void k_hist(const int* __restrict__ ei,
                                              const float* __restrict__ ea) {
    int base = blockIdx.x * 1024 + threadIdx.x;
    int sv[4], dv[4]; bool ok[4];
    #pragma unroll
    for (int i = 0; i < 4; i++) {
        int e = base + i * 256;
        ok[i] = e < EE;
        sv[i] = ok[i] ? ei[e] : 0;
        dv[i] = ok[i] ? ei[EE + e] : 0;
    }
    #pragma unroll
    for (int i = 0; i < 4; i++) {
        if (!ok[i]) continue;
        int e = base + i * 256;
        int c = dv[i] >> 2;
        unsigned enc = (unsigned)(sv[i] >> 2) * (unsigned)CC + (unsigned)c;
        unsigned wi = enc >> 6;
        atomicOr(&g_bitmap[wi], 1ull << (enc & 63));
        atomicOr(&g_summary[wi >> 6], 1ull << (wi & 63));
        atomicAdd(&g_hist[c], 1u);
        atomicAdd(&g_cagg_e[c * 4 + 0], ea[3 * e + 0]);
        atomicAdd(&g_cagg_e[c * 4 + 1], ea[3 * e + 1]);
        atomicAdd(&g_cagg_e[c * 4 + 2], ea[3 * e + 2]);
    }
}

// ---------------------------------------------------------------------------
__global__ __launch_bounds__(256) void k_scanH() {
    __shared__ unsigned s_warp[8];
    __shared__ unsigned sh_base;
    int b = blockIdx.x, tid = threadIdx.x;
    int idx = b * 256 + tid;
    unsigned v = (idx < CC) ? g_hist[idx] : 0u;
    unsigned total;
    unsigned excl = block_excl_scan256(v, s_warp, &total);
    if (tid < 32) {
        unsigned pf = lookback_warp(g_shState, b, total);
        if (tid == 0) sh_base = pf;
    }
    __syncthreads();
    if (idx < CC) {
        unsigned st = sh_base + excl;
        g_start[idx] = st;
        g_cursor[idx] = st;
    }
}

// ---------------------------------------------------------------------------
__global__ __launch_bounds__(256) void k_fill(const int* __restrict__ ei) {
    int base = blockIdx.x * 1024 + threadIdx.x;
    int sv[4]; unsigned p[4]; bool ok[4];
    #pragma unroll
    for (int i = 0; i < 4; i++) {
        int e = base + i * 256;
        ok[i] = e < EE;
        sv[i] = ok[i] ? ei[e] : 0;
        int c = ok[i] ? (ei[EE + e] >> 2) : 0;
        p[i] = ok[i] ? atomicAdd(&g_cursor[c], 1u) : 0u;
    }
    #pragma unroll
    for (int i = 0; i < 4; i++)
        if (ok[i]) g_binned_src[p[i]] = sv[i];
}

// ---------------------------------------------------------------------------
__global__ __launch_bounds__(256) void k_cluster() {
    int warp = (blockIdx.x * 256 + threadIdx.x) >> 5;
    int lane = threadIdx.x & 31;
    if (warp >= CC) return;
    unsigned base = g_start[warp];
    unsigned cnt = g_hist[warp];
    float4 acc = make_float4(0.f, 0.f, 0.f, 0.f);

    unsigned k = 0;
    for (; k + 32 <= cnt; k += 32) {
        int s = g_binned_src[base + k + lane];
        #pragma unroll
        for (int j = 0; j < 32; j++) {
            int sb = __shfl_sync(0xffffffffu, s, j);
            uint2 u = __ldg(&g_xh[sb * 32 + lane]);
            float2 f0 = __half22float2(*(__half2*)&u.x);
            float2 f1 = __half22float2(*(__half2*)&u.y);
            acc.x += f0.x; acc.y += f0.y; acc.z += f1.x; acc.w += f1.y;
        }
    }
    int rem = (int)(cnt - k);
    if (rem > 0) {
        int s = (lane < rem) ? g_binned_src[base + k + lane] : 0;
        for (int j = 0; j < rem; j++) {
            int sb = __shfl_sync(0xffffffffu, s, j);
            uint2 u = __ldg(&g_xh[sb * 32 + lane]);
            float2 f0 = __half22float2(*(__half2*)&u.x);
            float2 f1 = __half22float2(*(__half2*)&u.y);
            acc.x += f0.x; acc.y += f0.y; acc.z += f1.x; acc.w += f1.y;
        }
    }
    ((float4*)g_cagg_x)[(size_t)warp * 32 + lane] = acc;
}

// ---------------------------------------------------------------------------
__global__ __launch_bounds__(256) void k_uniq(float* __restrict__ out) {
    __shared__ unsigned s_warp[8];
    __shared__ unsigned sh_base;
    int b = blockIdx.x, tid = threadIdx.x;
    unsigned sIdx = (unsigned)b * 32u + (unsigned)(tid >> 3);
    unsigned long long sw = (sIdx < SUMW) ? g_summary[sIdx] : 0ull;
    unsigned sbyte = (unsigned)(sw >> ((tid & 7) * 8)) & 0xFFu;
    size_t wbase = (size_t)b * WPB + (size_t)tid * 8;

    unsigned long long w[8];
    unsigned cnt = 0;
    #pragma unroll
    for (int j = 0; j < 8; j++) {
        w[j] = (sbyte >> j) & 1u ? g_bitmap[wbase + j] : 0ull;
        cnt += (unsigned)__popcll(w[j]);
    }
    unsigned total;
    unsigned excl = block_excl_scan256(cnt, s_warp, &total);
    if (tid < 32) {
        unsigned pf = lookback_warp(g_ubState, b, total);
        if (tid == 0) sh_base = pf;
    }
    __syncthreads();
    if ((tid & 7) == 0 && sw) g_summary[sIdx] = 0ull;
    unsigned p = sh_base + excl;

    #pragma unroll
    for (int j = 0; j < 8; j++) {
        unsigned long long wv = w[j];
        if (!wv) continue;
        size_t wi = wbase + j;
        g_bitmap[wi] = 0ull;
        while (wv) {
            int bit = __ffsll((long long)wv) - 1;
            wv &= wv - 1;
            unsigned v = (unsigned)wi * 64u + (unsigned)bit;
            unsigned sc = v / (unsigned)CC;
            unsigned dc = v - sc * (unsigned)CC;
            out[IDX_OFF + p]      = (float)sc;
            out[IDX_OFF + EE + p] = (float)dc;
            out[ATTR_OFF + 3 * p + 0] = g_newpos[dc * 3 + 0] - g_newpos[sc * 3 + 0];
            out[ATTR_OFF + 3 * p + 1] = g_newpos[dc * 3 + 1] - g_newpos[sc * 3 + 1];
            out[ATTR_OFF + 3 * p + 2] = g_newpos[dc * 3 + 2] - g_newpos[sc * 3 + 2];
            p++;
        }
    }
}

// ---------------------------------------------------------------------------
__global__ __launch_bounds__(256) void k_tail(float* __restrict__ out) {
    unsigned U = g_ubState[NBLK - 1] & VALM;
    int t = blockIdx.x * 256 + threadIdx.x;
    const int S = 64 * 256;
    for (int p = U + t; p < EE; p += S) {
        out[IDX_OFF + p] = 0.f;
        out[IDX_OFF + EE + p] = 0.f;
        out[ATTR_OFF + 3 * p + 0] = 0.f;
        out[ATTR_OFF + 3 * p + 1] = 0.f;
        out[ATTR_OFF + 3 * p + 2] = 0.f;
    }
}

// ---------------------------------------------------------------------------
__global__ __launch_bounds__(256) void k_gemm(float* __restrict__ out) {
    __shared__ float s_rows[16][128];
    int col = threadIdx.x & 127;
    int ty = threadIdx.x >> 7;
    int r0 = blockIdx.x * 16;
    for (int i = threadIdx.x; i < 16 * 128; i += 256) {
        int rr = i >> 7, cc = i & 127;
        int gr = r0 + rr;
        s_rows[rr][cc] = (gr < CC) ? g_cagg_x[(size_t)gr * 128 + cc] : 0.f;
    }
    __syncthreads();
    float acc[8] = {0.f, 0.f, 0.f, 0.f, 0.f, 0.f, 0.f, 0.f};
    #pragma unroll 8
    for (int k = 0; k < 128; k += 4) {
        float w0 = __ldg(&g_W1[(k + 0) * 128 + col]);
        float w1 = __ldg(&g_W1[(k + 1) * 128 + col]);
        float w2 = __ldg(&g_W1[(k + 2) * 128 + col]);
        float w3 = __ldg(&g_W1[(k + 3) * 128 + col]);
        #pragma unroll
        for (int r = 0; r < 8; r++) {
            float4 cv = *(const float4*)&s_rows[ty * 8 + r][k];
            acc[r] += cv.x * w0 + cv.y * w1 + cv.z * w2 + cv.w * w3;
        }
    }
    float e0 = __ldg(&g_W2[0 * 128 + col]);
    float e1 = __ldg(&g_W2[1 * 128 + col]);
    float e2 = __ldg(&g_W2[2 * 128 + col]);
    #pragma unroll
    for (int r = 0; r < 8; r++) {
        int gr = r0 + ty * 8 + r;
        if (gr < CC) {
            float ce0 = g_cagg_e[gr * 4 + 0];
            float ce1 = g_cagg_e[gr * 4 + 1];
            float ce2 = g_cagg_e[gr * 4 + 2];
            float res = (acc[r] + ce0 * e0 + ce1 * e1 + ce2 * e2) * 0.25f;
            out[XNEW_OFF + (size_t)gr * 128 + col] = res;
        }
    }
}

// ---------------------------------------------------------------------------
extern "C" void kernel_launch(void* const* d_in, const int* in_sizes, int n_in,
                              void* d_out, int out_size) {
    const float* x   = (const float*)d_in[0];
    const float* pos = (const float*)d_in[1];
    const int*   ei  = (const int*)d_in[2];
    const float* ea  = (const float*)d_in[3];
    const int*   bat = (const int*)d_in[4];
    const float* Wc  = (const float*)d_in[5];
    const float* We  = (const float*)d_in[6];
    const float* Wg  = (const float*)d_in[8];
    float* out = (float*)d_out;

    static cudaStream_t s1 = nullptr, s2 = nullptr;
    static cudaEvent_t eT = nullptr, eF = nullptr, eJ = nullptr, eX = nullptr;
    if (s1 == nullptr) {
        cudaStreamCreate(&s1);
        cudaStreamCreate(&s2);
        cudaEventCreateWithFlags(&eT, cudaEventDisableTiming);
        cudaEventCreateWithFlags(&eF, cudaEventDisableTiming);
        cudaEventCreateWithFlags(&eJ, cudaEventDisableTiming);
        cudaEventCreateWithFlags(&eX, cudaEventDisableTiming);
    }

    cudaEventRecord(eT, 0);
    cudaStreamWaitEvent(s2, eT, 0);
    k_xh<<<3200, 256, 0, s2>>>(x);
    cudaEventRecord(eX, s2);

    k_init<<<269, 256>>>(pos, bat, Wc, We, Wg, out);
    k_hist<<<(EE + 1023) / 1024, 256>>>(ei, ea);

    cudaEventRecord(eF, 0);
    cudaStreamWaitEvent(s1, eF, 0);
    k_uniq<<<NBLK, 256, 0, s1>>>(out);
    k_tail<<<64, 256, 0, s1>>>(out);

    k_scanH<<<SHB, 256>>>();
    k_fill<<<(EE + 1023) / 1024, 256>>>(ei);
    cudaStreamWaitEvent(0, eX, 0);
    k_cluster<<<(CC * 32 + 255) / 256, 256>>>();
    k_gemm<<<(CC + 15) / 16, 256>>>(out);

    cudaEventRecord(eJ, s1);
    cudaStreamWaitEvent(0, eJ, 0);
}

// round 10
// speedup vs baseline: 1.2186x; 1.0157x over previous
#include <cuda_runtime.h>
#include <cuda_fp16.h>
#include <cstdint>

#define NN      100000
#define EE      1600000
#define CC      25000
#define PF      4
#define BM_WORDS 9765625u
#define SUMW     152588u
#define WPB      2048
#define NBLK     4769
#define SHB      98
#define SUB      19            // scanU blocks: 19*256 >= NBLK

#define XNEW_OFF  0
#define POS_OFF   3200000
#define IDX_OFF   3275000
#define ATTR_OFF  6475000
#define BATCH_OFF 11275000

#define VALM 0x3FFFFFFFu
#define AGGF 0x40000000u
#define PREF 0x80000000u

static __device__ unsigned long long g_bitmap[BM_WORDS];
static __device__ unsigned long long g_summary[SUMW];
static __device__ float    g_cagg_x[CC * 128];
static __device__ float    g_cagg_e[CC * 4];
static __device__ float    g_newpos[CC * 3];
static __device__ float    g_W1[128 * 128];
static __device__ float    g_W2[3 * 128];
static __device__ unsigned g_hist[CC];
static __device__ unsigned g_start[CC];
static __device__ unsigned g_cursor[CC];
static __device__ int      g_binned_src[EE];
static __device__ unsigned g_blockSums[NBLK];
static __device__ unsigned g_blockOffs[NBLK];
static __device__ unsigned g_shState[SHB];
static __device__ unsigned g_suState[SUB];
static __device__ uint2    g_xh[NN * 32];

// ---------------------------------------------------------------------------
// Warp-parallel decoupled lookback (warp 0 calls; all lanes get prefix)
__device__ __forceinline__ unsigned lookback_warp(unsigned* state, int b, unsigned agg) {
    int lane = threadIdx.x & 31;
    if (b == 0) {
        if (lane == 0) { __threadfence(); atomicExch(&state[0], PREF | agg); }
        return 0u;
    }
    if (lane == 0) atomicExch(&state[b], AGGF | agg);
    unsigned prefix = 0;
    int end = b;
    while (true) {
        int idx = end - 1 - lane;
        unsigned s;
        do {
            s = (idx >= 0) ? atomicAdd(&state[idx], 0u) : PREF;
        } while (!(s & (AGGF | PREF)));
        unsigned pmask = __ballot_sync(0xffffffffu, (s & PREF) != 0u);
        if (pmask) {
            int firstP = __ffs(pmask) - 1;
            unsigned contrib = (lane <= firstP) ? (s & VALM) : 0u;
            #pragma unroll
            for (int o = 16; o; o >>= 1) contrib += __shfl_down_sync(0xffffffffu, contrib, o);
            prefix += __shfl_sync(0xffffffffu, contrib, 0);
            break;
        } else {
            unsigned contrib = s & VALM;
            #pragma unroll
            for (int o = 16; o; o >>= 1) contrib += __shfl_down_sync(0xffffffffu, contrib, o);
            prefix += __shfl_sync(0xffffffffu, contrib, 0);
            end -= 32;
        }
    }
    if (lane == 0) { __threadfence(); atomicExch(&state[b], PREF | (agg + prefix)); }
    return prefix;
}

__device__ __forceinline__ unsigned block_excl_scan256(unsigned v, unsigned* s_warp,
                                                       unsigned* total) {
    unsigned lane = threadIdx.x & 31, wid = threadIdx.x >> 5;
    unsigned x = v;
    #pragma unroll
    for (int o = 1; o < 32; o <<= 1) {
        unsigned y = __shfl_up_sync(0xffffffffu, x, o);
        if (lane >= o) x += y;
    }
    if (lane == 31) s_warp[wid] = x;
    __syncthreads();
    if (wid == 0) {
        unsigned t = (lane < 8) ? s_warp[lane] : 0u;
        #pragma unroll
        for (int o = 1; o < 8; o <<= 1) {
            unsigned y = __shfl_up_sync(0xffffffffu, t, o);
            if (lane >= o) t += y;
        }
        if (lane < 8) s_warp[lane] = t;
    }
    __syncthreads();
    unsigned warpBase = wid ? s_warp[wid - 1] : 0u;
    unsigned excl = warpBase + x - v;
    *total = s_warp[7];
    __syncthreads();
    return excl;
}

// ---------------------------------------------------------------------------
__global__ __launch_bounds__(256) void k_xh(const float* __restrict__ x) {
    int t = blockIdx.x * 256 + threadIdx.x;
    const int TOT = NN * 32;
    const int S = gridDim.x * 256;
    const float4* x4 = (const float4*)x;
    for (int i = t; i < TOT; i += S) {
        float4 v = __ldg(&x4[i]);
        __half2 h0 = __floats2half2_rn(v.x, v.y);
        __half2 h1 = __floats2half2_rn(v.z, v.w);
        uint2 u;
        u.x = *(unsigned*)&h0;
        u.y = *(unsigned*)&h1;
        g_xh[i] = u;
    }
}

// ---------------------------------------------------------------------------
__global__ void k_init(const float* __restrict__ pos,
                       const int* __restrict__ batch,
                       const float* __restrict__ Wc,
                       const float* __restrict__ We,
                       const float* __restrict__ Wg,
                       float* __restrict__ out) {
    if (blockIdx.x < 98) {
        int c = blockIdx.x * 256 + threadIdx.x;
        if (c >= CC) return;
        float s0 = 0.f, s1 = 0.f, s2 = 0.f;
        int bmax = -2147483647;
        #pragma unroll
        for (int i = 0; i < PF; i++) {
            int n = c * PF + i;
            s0 += pos[n * 3 + 0];
            s1 += pos[n * 3 + 1];
            s2 += pos[n * 3 + 2];
            int b = batch[n];
            bmax = b > bmax ? b : bmax;
        }
        s0 *= 0.25f; s1 *= 0.25f; s2 *= 0.25f;
        g_newpos[c * 3 + 0] = s0;
        g_newpos[c * 3 + 1] = s1;
        g_newpos[c * 3 + 2] = s2;
        out[POS_OFF + c * 3 + 0] = s0;
        out[POS_OFF + c * 3 + 1] = s1;
        out[POS_OFF + c * 3 + 2] = s2;
        out[BATCH_OFF + c] = (float)bmax;
    } else if (blockIdx.x < 229) {
        int i = blockIdx.x - 98;
        int j = threadIdx.x;
        if (j >= 128) return;
        if (i < 128) {
            float s = 0.f;
            #pragma unroll 8
            for (int k = 0; k < 128; k++) s += Wc[i * 144 + 16 + k] * Wg[k * 128 + j];
            g_W1[i * 128 + j] = s;
        } else {
            int r = i - 128;
            float s = 0.f;
            #pragma unroll 8
            for (int k = 0; k < 128; k++) s += We[r * 144 + 16 + k] * Wg[k * 128 + j];
            g_W2[r * 128 + j] = s;
        }
    } else {
        int t = (blockIdx.x - 229) * 256 + threadIdx.x;
        const int S = 40 * 256;
        for (int i = t; i < CC * 4; i += S) g_cagg_e[i] = 0.f;
        for (int i = t; i < CC; i += S) g_hist[i] = 0u;
        for (int i = t; i < SHB; i += S) g_shState[i] = 0u;
        for (int i = t; i < SUB; i += S) g_suState[i] = 0u;
    }
}

// ---------------------------------------------------------------------------
__global__ __launch_bounds__(256) void k_hist(const int* __restrict__ ei,
                                              const float* __restrict__ ea) {
    int base = blockIdx.x * 1024 + threadIdx.x;
    int sv[4], dv[4]; bool ok[4];
    #pragma unroll
    for (int i = 0; i < 4; i++) {
        int e = base + i * 256;
        ok[i] = e < EE;
        sv[i] = ok[i] ? ei[e] : 0;
        dv[i] = ok[i] ? ei[EE + e] : 0;
    }
    #pragma unroll
    for (int i = 0; i < 4; i++) {
        if (!ok[i]) continue;
        int e = base + i * 256;
        int c = dv[i] >> 2;
        unsigned enc = (unsigned)(sv[i] >> 2) * (unsigned)CC + (unsigned)c;
        unsigned wi = enc >> 6;
        atomicOr(&g_bitmap[wi], 1ull << (enc & 63));
        atomicOr(&g_summary[wi >> 6], 1ull << (wi & 63));
        atomicAdd(&g_hist[c], 1u);
        atomicAdd(&g_cagg_e[c * 4 + 0], ea[3 * e + 0]);
        atomicAdd(&g_cagg_e[c * 4 + 1], ea[3 * e + 1]);
        atomicAdd(&g_cagg_e[c * 4 + 2], ea[3 * e + 2]);
    }
}

// ---------------------------------------------------------------------------
__global__ __launch_bounds__(256) void k_scanH() {
    __shared__ unsigned s_warp[8];
    __shared__ unsigned sh_base;
    int b = blockIdx.x, tid = threadIdx.x;
    int idx = b * 256 + tid;
    unsigned v = (idx < CC) ? g_hist[idx] : 0u;
    unsigned total;
    unsigned excl = block_excl_scan256(v, s_warp, &total);
    if (tid < 32) {
        unsigned pf = lookback_warp(g_shState, b, total);
        if (tid == 0) sh_base = pf;
    }
    __syncthreads();
    if (idx < CC) {
        unsigned st = sh_base + excl;
        g_start[idx] = st;
        g_cursor[idx] = st;
    }
}

// ---------------------------------------------------------------------------
__global__ __launch_bounds__(256) void k_fill(const int* __restrict__ ei) {
    int base = blockIdx.x * 1024 + threadIdx.x;
    int sv[4]; unsigned p[4]; bool ok[4];
    #pragma unroll
    for (int i = 0; i < 4; i++) {
        int e = base + i * 256;
        ok[i] = e < EE;
        sv[i] = ok[i] ? ei[e] : 0;
        int c = ok[i] ? (ei[EE + e] >> 2) : 0;
        p[i] = ok[i] ? atomicAdd(&g_cursor[c], 1u) : 0u;
    }
    #pragma unroll
    for (int i = 0; i < 4; i++)
        if (ok[i]) g_binned_src[p[i]] = sv[i];
}

// ---------------------------------------------------------------------------
// K_cluster: one warp per cluster; fp16 gather, fp32 dual accumulators
__global__ __launch_bounds__(256) void k_cluster() {
    int warp = (blockIdx.x * 256 + threadIdx.x) >> 5;
    int lane = threadIdx.x & 31;
    if (warp >= CC) return;
    unsigned base = g_start[warp];
    unsigned cnt = g_hist[warp];
    float4 a0 = make_float4(0.f, 0.f, 0.f, 0.f);
    float4 a1 = make_float4(0.f, 0.f, 0.f, 0.f);

    unsigned k = 0;
    for (; k + 32 <= cnt; k += 32) {
        int s = g_binned_src[base + k + lane];
        #pragma unroll
        for (int j = 0; j < 32; j += 2) {
            int s0 = __shfl_sync(0xffffffffu, s, j);
            int s1 = __shfl_sync(0xffffffffu, s, j + 1);
            uint2 u0 = __ldg(&g_xh[s0 * 32 + lane]);
            uint2 u1 = __ldg(&g_xh[s1 * 32 + lane]);
            float2 p0 = __half22float2(*(__half2*)&u0.x);
            float2 p1 = __half22float2(*(__half2*)&u0.y);
            float2 q0 = __half22float2(*(__half2*)&u1.x);
            float2 q1 = __half22float2(*(__half2*)&u1.y);
            a0.x += p0.x; a0.y += p0.y; a0.z += p1.x; a0.w += p1.y;
            a1.x += q0.x; a1.y += q0.y; a1.z += q1.x; a1.w += q1.y;
        }
    }
    int rem = (int)(cnt - k);
    if (rem > 0) {
        int s = (lane < rem) ? g_binned_src[base + k + lane] : 0;
        for (int j = 0; j < rem; j++) {
            int sb = __shfl_sync(0xffffffffu, s, j);
            uint2 u = __ldg(&g_xh[sb * 32 + lane]);
            float2 f0 = __half22float2(*(__half2*)&u.x);
            float2 f1 = __half22float2(*(__half2*)&u.y);
            a0.x += f0.x; a0.y += f0.y; a0.z += f1.x; a0.w += f1.y;
        }
    }
    a0.x += a1.x; a0.y += a1.y; a0.z += a1.z; a0.w += a1.w;
    ((float4*)g_cagg_x)[(size_t)warp * 32 + lane] = a0;
}

// ---------------------------------------------------------------------------
// K_count: summary-guided popcount per block (no inter-block dependency)
__global__ __launch_bounds__(256) void k_count() {
    __shared__ unsigned s_sum[8];
    int b = blockIdx.x, tid = threadIdx.x;
    unsigned sIdx = (unsigned)b * 32u + (unsigned)(tid >> 3);
    unsigned long long sw = (sIdx < SUMW) ? g_summary[sIdx] : 0ull;
    unsigned sbyte = (unsigned)(sw >> ((tid & 7) * 8)) & 0xFFu;
    size_t wbase = (size_t)b * WPB + (size_t)tid * 8;
    unsigned cnt = 0;
    #pragma unroll
    for (int j = 0; j < 8; j++)
        if ((sbyte >> j) & 1u) cnt += (unsigned)__popcll(g_bitmap[wbase + j]);
    #pragma unroll
    for (int o = 16; o; o >>= 1) cnt += __shfl_down_sync(0xffffffffu, cnt, o);
    if ((tid & 31) == 0) s_sum[tid >> 5] = cnt;
    __syncthreads();
    if (tid == 0) {
        unsigned t = 0;
        #pragma unroll
        for (int i = 0; i < 8; i++) t += s_sum[i];
        g_blockSums[b] = t;
    }
}

// ---------------------------------------------------------------------------
// K_scanU: exclusive scan of 4769 block sums (19 blocks, shallow lookback)
__global__ __launch_bounds__(256) void k_scanU() {
    __shared__ unsigned s_warp[8];
    __shared__ unsigned sh_base;
    int b = blockIdx.x, tid = threadIdx.x;
    int idx = b * 256 + tid;
    unsigned v = (idx < NBLK) ? g_blockSums[idx] : 0u;
    unsigned total;
    unsigned excl = block_excl_scan256(v, s_warp, &total);
    if (tid < 32) {
        unsigned pf = lookback_warp(g_suState, b, total);
        if (tid == 0) sh_base = pf;
    }
    __syncthreads();
    if (idx < NBLK) g_blockOffs[idx] = sh_base + excl;
}

// ---------------------------------------------------------------------------
// K_emit: summary-guided sorted emit using precomputed offsets; self-cleans
__global__ __launch_bounds__(256) void k_emit(float* __restrict__ out) {
    __shared__ unsigned s_warp[8];
    int b = blockIdx.x, tid = threadIdx.x;
    unsigned sIdx = (unsigned)b * 32u + (unsigned)(tid >> 3);
    unsigned long long sw = (sIdx < SUMW) ? g_summary[sIdx] : 0ull;
    unsigned sbyte = (unsigned)(sw >> ((tid & 7) * 8)) & 0xFFu;
    size_t wbase = (size_t)b * WPB + (size_t)tid * 8;

    unsigned long long w[8];
    unsigned cnt = 0;
    #pragma unroll
    for (int j = 0; j < 8; j++) {
        w[j] = (sbyte >> j) & 1u ? g_bitmap[wbase + j] : 0ull;
        cnt += (unsigned)__popcll(w[j]);
    }
    unsigned total;
    unsigned excl = block_excl_scan256(cnt, s_warp, &total);
    if ((tid & 7) == 0 && sw) g_summary[sIdx] = 0ull;   // all co-readers past loads
    unsigned p = g_blockOffs[b] + excl;

    #pragma unroll
    for (int j = 0; j < 8; j++) {
        unsigned long long wv = w[j];
        if (!wv) continue;
        size_t wi = wbase + j;
        g_bitmap[wi] = 0ull;
        while (wv) {
            int bit = __ffsll((long long)wv) - 1;
            wv &= wv - 1;
            unsigned v = (unsigned)wi * 64u + (unsigned)bit;
            unsigned sc = v / (unsigned)CC;
            unsigned dc = v - sc * (unsigned)CC;
            out[IDX_OFF + p]      = (float)sc;
            out[IDX_OFF + EE + p] = (float)dc;
            out[ATTR_OFF + 3 * p + 0] = g_newpos[dc * 3 + 0] - g_newpos[sc * 3 + 0];
            out[ATTR_OFF + 3 * p + 1] = g_newpos[dc * 3 + 1] - g_newpos[sc * 3 + 1];
            out[ATTR_OFF + 3 * p + 2] = g_newpos[dc * 3 + 2] - g_newpos[sc * 3 + 2];
            p++;
        }
    }
}

// ---------------------------------------------------------------------------
__global__ __launch_bounds__(256) void k_tail(float* __restrict__ out) {
    unsigned U = g_blockOffs[NBLK - 1] + g_blockSums[NBLK - 1];
    int t = blockIdx.x * 256 + threadIdx.x;
    const int S = 64 * 256;
    for (int p = U + t; p < EE; p += S) {
        out[IDX_OFF + p] = 0.f;
        out[IDX_OFF + EE + p] = 0.f;
        out[ATTR_OFF + 3 * p + 0] = 0.f;
        out[ATTR_OFF + 3 * p + 1] = 0.f;
        out[ATTR_OFF + 3 * p + 2] = 0.f;
    }
}

// ---------------------------------------------------------------------------
__global__ __launch_bounds__(256) void k_gemm(float* __restrict__ out) {
    __shared__ float s_rows[16][128];
    int col = threadIdx.x & 127;
    int ty = threadIdx.x >> 7;
    int r0 = blockIdx.x * 16;
    for (int i = threadIdx.x; i < 16 * 128; i += 256) {
        int rr = i >> 7, cc = i & 127;
        int gr = r0 + rr;
        s_rows[rr][cc] = (gr < CC) ? g_cagg_x[(size_t)gr * 128 + cc] : 0.f;
    }
    __syncthreads();
    float acc[8] = {0.f, 0.f, 0.f, 0.f, 0.f, 0.f, 0.f, 0.f};
    #pragma unroll 8
    for (int k = 0; k < 128; k += 4) {
        float w0 = __ldg(&g_W1[(k + 0) * 128 + col]);
        float w1 = __ldg(&g_W1[(k + 1) * 128 + col]);
        float w2 = __ldg(&g_W1[(k + 2) * 128 + col]);
        float w3 = __ldg(&g_W1[(k + 3) * 128 + col]);
        #pragma unroll
        for (int r = 0; r < 8; r++) {
            float4 cv = *(const float4*)&s_rows[ty * 8 + r][k];
            acc[r] += cv.x * w0 + cv.y * w1 + cv.z * w2 + cv.w * w3;
        }
    }
    float e0 = __ldg(&g_W2[0 * 128 + col]);
    float e1 = __ldg(&g_W2[1 * 128 + col]);
    float e2 = __ldg(&g_W2[2 * 128 + col]);
    #pragma unroll
    for (int r = 0; r < 8; r++) {
        int gr = r0 + ty * 8 + r;
        if (gr < CC) {
            float ce0 = g_cagg_e[gr * 4 + 0];
            float ce1 = g_cagg_e[gr * 4 + 1];
            float ce2 = g_cagg_e[gr * 4 + 2];
            float res = (acc[r] + ce0 * e0 + ce1 * e1 + ce2 * e2) * 0.25f;
            out[XNEW_OFF + (size_t)gr * 128 + col] = res;
        }
    }
}

// ---------------------------------------------------------------------------
extern "C" void kernel_launch(void* const* d_in, const int* in_sizes, int n_in,
                              void* d_out, int out_size) {
    const float* x   = (const float*)d_in[0];
    const float* pos = (const float*)d_in[1];
    const int*   ei  = (const int*)d_in[2];
    const float* ea  = (const float*)d_in[3];
    const int*   bat = (const int*)d_in[4];
    const float* Wc  = (const float*)d_in[5];
    const float* We  = (const float*)d_in[6];
    const float* Wg  = (const float*)d_in[8];
    float* out = (float*)d_out;

    static cudaStream_t s1 = nullptr, s2 = nullptr;
    static cudaEvent_t eT = nullptr, eF = nullptr, eJ = nullptr, eX = nullptr;
    if (s1 == nullptr) {
        cudaStreamCreate(&s1);
        cudaStreamCreate(&s2);
        cudaEventCreateWithFlags(&eT, cudaEventDisableTiming);
        cudaEventCreateWithFlags(&eF, cudaEventDisableTiming);
        cudaEventCreateWithFlags(&eJ, cudaEventDisableTiming);
        cudaEventCreateWithFlags(&eX, cudaEventDisableTiming);
    }

    cudaEventRecord(eT, 0);
    cudaStreamWaitEvent(s2, eT, 0);
    k_xh<<<3200, 256, 0, s2>>>(x);
    cudaEventRecord(eX, s2);

    k_init<<<269, 256>>>(pos, bat, Wc, We, Wg, out);
    k_hist<<<(EE + 1023) / 1024, 256>>>(ei, ea);

    cudaEventRecord(eF, 0);
    cudaStreamWaitEvent(s1, eF, 0);
    k_count<<<NBLK, 256, 0, s1>>>();
    k_scanU<<<SUB, 256, 0, s1>>>();
    k_emit<<<NBLK, 256, 0, s1>>>(out);
    k_tail<<<64, 256, 0, s1>>>(out);

    k_scanH<<<SHB, 256>>>();
    k_fill<<<(EE + 1023) / 1024, 256>>>(ei);
    cudaStreamWaitEvent(0, eX, 0);
    k_cluster<<<(CC * 32 + 255) / 256, 256>>>();
    k_gemm<<<(CC + 15) / 16, 256>>>(out);

    cudaEventRecord(eJ, s1);
    cudaStreamWaitEvent(0, eJ, 0);
}